// round 15
// baseline (speedup 1.0000x reference)
#include <cuda_runtime.h>
#include <cuda_fp16.h>
#include <cstdint>
#include <math.h>

// ============================================================================
// MoE (top-2 of 8 experts), D=1024, H=4096, O=1024, T=8192 tokens.
// GEMMs: mma.sync fp16 m16n8k16 fp32-acc, R11 core (CTA tile 128x256, BK=64,
// 8 warps 2Mx4N, fragment double-buffer, 4-stage cp.async) wrapped in a
// PERSISTENT work-stealing loop (one CTA per SM, global tile queue) to kill
// wave quantization + tail idle. w2conv overlaps GEMM1; router/scatter
// overlap w1conv (side streams).
// ============================================================================

#define T_TOK   8192
#define DMODEL  1024
#define DHID    4096
#define DOUTD   1024
#define NEXP    8
#define ROWS_CAP 17408

#define BM 128
#define BN 256
#define BK 64                               // halfs per chunk = 128 B per row

#define SMEM_A_BYTES (BM * BK * 2)          // 16384
#define SMEM_B_BYTES (BN * BK * 2)          // 32768
#define SMEM_STAGE   (SMEM_A_BYTES + SMEM_B_BYTES)  // 49152
#define NSTAGE 4
#define DSMEM_BYTES  (NSTAGE * SMEM_STAGE)  // 196608

// ---------------- device scratch ----------------
__device__ __half g_perm[(size_t)ROWS_CAP * DMODEL];
__device__ __half g_h   [(size_t)ROWS_CAP * DHID];
__device__ float  g_y   [(size_t)ROWS_CAP * DOUTD];
__device__ __half g_w1h [(size_t)NEXP * DHID * DMODEL];
__device__ __half g_w2h [(size_t)NEXP * DOUTD * DHID];
__device__ float g_probs[T_TOK * NEXP];
__device__ float g_gate [T_TOK * 2];
__device__ int   g_topk [T_TOK * 2];
__device__ int   g_spos [T_TOK * 2];
__device__ int   g_counts[NEXP];   // zero-init; reset by setup for next replay
__device__ int   g_cursor[NEXP];
__device__ int   g_offsets[NEXP + 1];
__device__ float g_lb[1];
__device__ int   g_done;
__device__ int   g_tileq[2];       // work queues (GEMM1, GEMM2); reset in setup

// ---------------- PTX helpers ----------------
__device__ __forceinline__ uint32_t smem_to_u32(const void* p) {
    uint32_t a;
    asm("{ .reg .u64 t; cvta.to.shared.u64 t, %1; cvt.u32.u64 %0, t; }" : "=r"(a) : "l"(p));
    return a;
}
__device__ __forceinline__ uint32_t f2h2(float lo, float hi) {
    uint32_t r;
    asm("cvt.rn.f16x2.f32 %0, %1, %2;" : "=r"(r) : "f"(hi), "f"(lo));
    return r;
}
__device__ __forceinline__ uint32_t lds_u(uint32_t a) {
    uint32_t v;
    asm volatile("ld.shared.b32 %0, [%1];" : "=r"(v) : "r"(a));
    return v;
}
#define CP_ASYNC16(dst, src) \
    asm volatile("cp.async.cg.shared.global [%0], [%1], 16;" :: "r"(dst), "l"(src) : "memory")
#define CP_COMMIT() asm volatile("cp.async.commit_group;" ::: "memory")
#define CP_WAIT2()  asm volatile("cp.async.wait_group 2;" ::: "memory")
#define CP_WAIT1()  asm volatile("cp.async.wait_group 1;" ::: "memory")
#define CP_WAIT0()  asm volatile("cp.async.wait_group 0;" ::: "memory")

__device__ __forceinline__ void mma16816(float* c, const uint32_t* a, uint32_t b0, uint32_t b1) {
    asm volatile(
        "mma.sync.aligned.m16n8k16.row.col.f32.f16.f16.f32 "
        "{%0,%1,%2,%3}, {%4,%5,%6,%7}, {%8,%9}, {%0,%1,%2,%3};"
        : "+f"(c[0]), "+f"(c[1]), "+f"(c[2]), "+f"(c[3])
        : "r"(a[0]), "r"(a[1]), "r"(a[2]), "r"(a[3]), "r"(b0), "r"(b1));
}

// ============================================================================
// fp32 -> fp16 weight conversion kernels
// ============================================================================
__global__ void w1conv_kernel(const float* __restrict__ w1, __half* __restrict__ w1h) {
    const int n4 = NEXP * DHID * DMODEL / 4;
    int stride = gridDim.x * blockDim.x;
    for (int i = blockIdx.x * blockDim.x + threadIdx.x; i < n4; i += stride) {
        float4 v = ((const float4*)w1)[i];
        ((uint2*)w1h)[i] = make_uint2(f2h2(v.x, v.y), f2h2(v.z, v.w));
    }
}
__global__ void w2conv_kernel(const float* __restrict__ w2, __half* __restrict__ w2h) {
    const int n4 = NEXP * DOUTD * DHID / 4;
    int stride = gridDim.x * blockDim.x;
    for (int i = blockIdx.x * blockDim.x + threadIdx.x; i < n4; i += stride) {
        float4 u = ((const float4*)w2)[i];
        ((uint2*)w2h)[i] = make_uint2(f2h2(u.x, u.y), f2h2(u.z, u.w));
    }
}

// ============================================================================
// router + (last block) setup (also resets tile queues for the GEMMs)
// ============================================================================
__global__ void router_kernel(const float* __restrict__ x, const float* __restrict__ rw,
                              const float* __restrict__ rb) {
    int warp = threadIdx.x >> 5, lane = threadIdx.x & 31;
    int t = blockIdx.x * 8 + warp;
    const float* xp = x + (size_t)t * DMODEL;
    float xr[32];
#pragma unroll
    for (int i = 0; i < 32; i++) xr[i] = xp[i * 32 + lane];
    float lg[NEXP];
#pragma unroll
    for (int e = 0; e < NEXP; e++) {
        const float* wp = rw + e * DMODEL;
        float s = 0.f;
#pragma unroll
        for (int i = 0; i < 32; i++) s += xr[i] * wp[i * 32 + lane];
#pragma unroll
        for (int o = 16; o; o >>= 1) s += __shfl_xor_sync(0xFFFFFFFFu, s, o);
        lg[e] = s + rb[e];
    }
    if (lane == 0) {
        float mx = lg[0];
#pragma unroll
        for (int e = 1; e < NEXP; e++) mx = fmaxf(mx, lg[e]);
        float p[NEXP], sum = 0.f;
#pragma unroll
        for (int e = 0; e < NEXP; e++) { p[e] = expf(lg[e] - mx); sum += p[e]; }
        float inv = 1.f / sum;
#pragma unroll
        for (int e = 0; e < NEXP; e++) { p[e] *= inv; g_probs[t * NEXP + e] = p[e]; }
        int i0 = 0;
#pragma unroll
        for (int e = 1; e < NEXP; e++) if (p[e] > p[i0]) i0 = e;
        int i1 = (i0 == 0) ? 1 : 0;
#pragma unroll
        for (int e = 0; e < NEXP; e++) if (e != i0 && e != i1 && p[e] > p[i1]) i1 = e;
        float w0 = p[i0], w1 = p[i1], ws = 1.f / (w0 + w1);
        g_gate[t * 2 + 0] = w0 * ws;
        g_gate[t * 2 + 1] = w1 * ws;
        g_topk[t * 2 + 0] = i0;
        g_topk[t * 2 + 1] = i1;
        atomicAdd(&g_counts[i0], 1);
        atomicAdd(&g_counts[i1], 1);
        __threadfence();
    }
    __syncthreads();
    __shared__ int s_last;
    if (threadIdx.x == 0) {
        int old = atomicAdd(&g_done, 1);
        s_last = (old == gridDim.x - 1);
    }
    __syncthreads();
    if (!s_last) return;

    __shared__ float sp[NEXP];
    if (warp < NEXP) {
        float s = 0.f;
        for (int tt = lane; tt < T_TOK; tt += 32) s += __ldcg(&g_probs[tt * NEXP + warp]);
#pragma unroll
        for (int o = 16; o; o >>= 1) s += __shfl_xor_sync(0xFFFFFFFFu, s, o);
        if (lane == 0) sp[warp] = s;
    }
    __syncthreads();
    if (threadIdx.x == 0) {
        int off = 0;
        float l = 0.f;
        for (int e = 0; e < NEXP; e++) {
            int c = __ldcg(&g_counts[e]);
            g_offsets[e] = off;
            off += ((c + BM - 1) / BM) * BM;
            g_cursor[e] = 0;
            g_counts[e] = 0;   // reset for next graph replay
            l += ((float)c / (float)(T_TOK * 2)) * (sp[e] / (float)T_TOK);
        }
        g_offsets[NEXP] = off;
        g_lb[0] = 0.01f * (float)NEXP * l;
        g_tileq[0] = 0;        // reset GEMM work queues for this replay
        g_tileq[1] = 0;
        g_done = 0;
    }
}

// ============================================================================
// gather: converts x rows to fp16 in grouped layout
// ============================================================================
__global__ void scatter_kernel(const float* __restrict__ x) {
    int wslot = blockIdx.x * 8 + (threadIdx.x >> 5);
    int lane = threadIdx.x & 31;
    int t = wslot >> 1, k = wslot & 1;
    int e = g_topk[t * 2 + k];
    int pos = 0;
    if (lane == 0) {
        pos = g_offsets[e] + atomicAdd(&g_cursor[e], 1);
        g_spos[t * 2 + k] = pos;
    }
    pos = __shfl_sync(0xFFFFFFFFu, pos, 0);
    const float4* src = (const float4*)(x + (size_t)t * DMODEL);
    uint2* dst = (uint2*)(g_perm + (size_t)pos * DMODEL);
#pragma unroll
    for (int j = 0; j < 8; j++) {
        float4 v = src[lane + j * 32];
        dst[lane + j * 32] = make_uint2(f2h2(v.x, v.y), f2h2(v.z, v.w));
    }
}

// ============================================================================
// PERSISTENT grouped fp16 GEMM. One CTA per SM; tiles pulled from g_tileq.
// Tile id -> (row tile, n tile); consecutive ids share row0 (A stays in L2).
// MODE 0: A=g_perm -> C=g_h (relu, fp16). MODE 1: A=g_h -> C=g_y (f32).
// ============================================================================
template <int KTOT, int NTOT, bool RELU, int MODE>
__global__ __launch_bounds__(256, 1) void gemm_kernel(const __half* __restrict__ Bw,
                                                      const float* __restrict__ bias) {
    const __half* A = (MODE == 0) ? g_perm : g_h;
    constexpr int NTX = NTOT / BN;

    extern __shared__ char smem[];
    uint32_t sb = smem_to_u32(smem);
    int tid = threadIdx.x;
    int wid = tid >> 5, lane = tid & 31;
    int g = lane >> 2, t = lane & 3;
    int wm = wid >> 2;
    int wn = wid & 3;

    __shared__ int s_tile;
    const int ntiles = (g_offsets[NEXP] >> 7) * NTX;

    for (;;) {
        if (tid == 0) s_tile = atomicAdd(&g_tileq[MODE], 1);
        __syncthreads();          // epilogue of prev tile done + s_tile visible
        int tile = s_tile;
        if (tile >= ntiles) return;

        int row0 = (tile / NTX) * BM;
        int n0 = (tile % NTX) * BN;
        int e = 0;
#pragma unroll
        for (int i = 1; i < NEXP; i++) if (row0 >= g_offsets[i]) e = i;

        const __half* Ag = A + (size_t)row0 * KTOT;
        const __half* Bg = Bw + (size_t)e * NTOT * KTOT + (size_t)n0 * KTOT;

        auto load_chunk = [&](int it, int buf) {
            int k0 = it * BK;
            uint32_t sA = sb + buf * SMEM_STAGE;
            uint32_t sB = sA + SMEM_A_BYTES;
#pragma unroll
            for (int i = 0; i < 4; i++) {       // A: 128 rows x 8 x 16B
                int idx = tid + i * 256;
                int r = idx >> 3, c8 = idx & 7;
                uint32_t dst = sA + (uint32_t)(r * 8 + (c8 ^ (r & 7))) * 16;
                CP_ASYNC16(dst, Ag + (size_t)r * KTOT + k0 + c8 * 8);
            }
#pragma unroll
            for (int i = 0; i < 8; i++) {       // B: 256 rows x 8 x 16B
                int idx = tid + i * 256;
                int r = idx >> 3, c8 = idx & 7;
                uint32_t dst = sB + (uint32_t)(r * 8 + (c8 ^ (r & 7))) * 16;
                CP_ASYNC16(dst, Bg + (size_t)r * KTOT + k0 + c8 * 8);
            }
            CP_COMMIT();
        };

        float acc[4][8][4];
#pragma unroll
        for (int mt = 0; mt < 4; mt++)
#pragma unroll
            for (int nt = 0; nt < 8; nt++)
#pragma unroll
                for (int j = 0; j < 4; j++) acc[mt][nt][j] = 0.f;

        constexpr int NIT = KTOT / BK;
        load_chunk(0, 0);
        load_chunk(1, 1);
        load_chunk(2, 2);

        for (int it = 0; it < NIT; ++it) {
            int buf = it & 3;
            if (it < NIT - 2)      { CP_WAIT2(); }
            else if (it == NIT - 2){ CP_WAIT1(); }
            else                   { CP_WAIT0(); }
            __syncthreads();
            if (it + 3 < NIT) load_chunk(it + 3, (it + 3) & 3);

            uint32_t sA = sb + buf * SMEM_STAGE;
            uint32_t sB = sA + SMEM_A_BYTES;

            auto lfrag = [&](int kk, uint32_t* a_f, uint32_t* b_f) {
                uint32_t col0 = (uint32_t)(((2 * kk) ^ g) * 16 + t * 4);
                uint32_t col1 = (uint32_t)(((2 * kk + 1) ^ g) * 16 + t * 4);
#pragma unroll
                for (int mt = 0; mt < 4; mt++) {
                    uint32_t r0 = (uint32_t)(wm * 64 + mt * 16 + g) * 128;
                    a_f[mt * 4 + 0] = lds_u(sA + r0 + col0);
                    a_f[mt * 4 + 1] = lds_u(sA + r0 + 8 * 128 + col0);
                    a_f[mt * 4 + 2] = lds_u(sA + r0 + col1);
                    a_f[mt * 4 + 3] = lds_u(sA + r0 + 8 * 128 + col1);
                }
#pragma unroll
                for (int nt = 0; nt < 8; nt++) {
                    uint32_t rn = (uint32_t)(wn * 64 + nt * 8 + g) * 128;
                    b_f[nt * 2 + 0] = lds_u(sB + rn + col0);
                    b_f[nt * 2 + 1] = lds_u(sB + rn + col1);
                }
            };

            uint32_t afr[2][16], bfr[2][16];
            lfrag(0, afr[0], bfr[0]);
#pragma unroll
            for (int kk = 0; kk < 4; kk++) {
                int cur = kk & 1;
                if (kk < 3) lfrag(kk + 1, afr[cur ^ 1], bfr[cur ^ 1]);
#pragma unroll
                for (int nt = 0; nt < 8; nt++)
#pragma unroll
                    for (int mt = 0; mt < 4; mt++)
                        mma16816(acc[mt][nt], &afr[cur][mt * 4],
                                 bfr[cur][nt * 2], bfr[cur][nt * 2 + 1]);
            }
        }

        // ---- epilogue (registers + global only; no smem) ----
        const float* bp = bias + (size_t)e * NTOT + n0 + wn * 64;
#pragma unroll
        for (int nt = 0; nt < 8; nt++) {
            int col = nt * 8 + 2 * t;
            float2 bv = *(const float2*)(bp + col);
#pragma unroll
            for (int mt = 0; mt < 4; mt++) {
                int r0 = row0 + wm * 64 + mt * 16 + g;
                float v[4];
                v[0] = acc[mt][nt][0] + bv.x; v[1] = acc[mt][nt][1] + bv.y;
                v[2] = acc[mt][nt][2] + bv.x; v[3] = acc[mt][nt][3] + bv.y;
                if (RELU) {
#pragma unroll
                    for (int j = 0; j < 4; j++) v[j] = fmaxf(v[j], 0.f);
                }
                if (MODE == 0) {
                    uint32_t* cp0 = (uint32_t*)(g_h + (size_t)r0 * NTOT + n0 + wn * 64 + col);
                    cp0[0] = f2h2(v[0], v[1]);
                    *(uint32_t*)((__half*)cp0 + (size_t)8 * NTOT) = f2h2(v[2], v[3]);
                } else {
                    float* cp0 = g_y + (size_t)r0 * NTOT + n0 + wn * 64 + col;
                    *(float2*)cp0 = make_float2(v[0], v[1]);
                    *(float2*)(cp0 + (size_t)8 * NTOT) = make_float2(v[2], v[3]);
                }
            }
        }
    }
}

// ============================================================================
// combine (+ lb tail written by the extra trailing block)
// ============================================================================
__global__ void combine_kernel(float* __restrict__ out, int out_size) {
    int t = blockIdx.x;
    if (t >= T_TOK) {
        long long tail = (long long)out_size - (long long)T_TOK * DOUTD;
        if (threadIdx.x < tail && threadIdx.x < 256)
            out[(size_t)T_TOK * DOUTD + threadIdx.x] = g_lb[0];
        return;
    }
    int d4 = threadIdx.x;
    float w0 = g_gate[t * 2 + 0], w1 = g_gate[t * 2 + 1];
    int p0 = g_spos[t * 2 + 0], p1 = g_spos[t * 2 + 1];
    float4 y0 = ((const float4*)(g_y + (size_t)p0 * DOUTD))[d4];
    float4 y1 = ((const float4*)(g_y + (size_t)p1 * DOUTD))[d4];
    float4 o;
    o.x = w0 * y0.x + w1 * y1.x;
    o.y = w0 * y0.y + w1 * y1.y;
    o.z = w0 * y0.z + w1 * y1.z;
    o.w = w0 * y0.w + w1 * y1.w;
    ((float4*)(out + (size_t)t * DOUTD))[d4] = o;
}

// ============================================================================
extern "C" void kernel_launch(void* const* d_in, const int* in_sizes, int n_in,
                              void* d_out, int out_size) {
    const float* x  = (const float*)d_in[0];
    const float* rw = (const float*)d_in[1];
    const float* rb = (const float*)d_in[2];
    const float* w1 = (const float*)d_in[3];
    const float* b1 = (const float*)d_in[4];
    const float* w2 = (const float*)d_in[5];
    const float* b2 = (const float*)d_in[6];
    float* out = (float*)d_out;

    cudaFuncSetAttribute(gemm_kernel<DMODEL, DHID, true, 0>,
                         cudaFuncAttributeMaxDynamicSharedMemorySize, DSMEM_BYTES);
    cudaFuncSetAttribute(gemm_kernel<DHID, DOUTD, false, 1>,
                         cudaFuncAttributeMaxDynamicSharedMemorySize, DSMEM_BYTES);

    int nsm = 148;
    {
        int dev = 0;
        cudaGetDevice(&dev);
        cudaDeviceGetAttribute(&nsm, cudaDevAttrMultiProcessorCount, dev);
    }

    __half* w1h; cudaGetSymbolAddress((void**)&w1h, g_w1h);
    __half* w2h; cudaGetSymbolAddress((void**)&w2h, g_w2h);

    cudaStream_t s1, s2;
    cudaStreamCreateWithFlags(&s1, cudaStreamNonBlocking);
    cudaStreamCreateWithFlags(&s2, cudaStreamNonBlocking);
    cudaEvent_t evFork, evScat, evW2;
    cudaEventCreateWithFlags(&evFork, cudaEventDisableTiming);
    cudaEventCreateWithFlags(&evScat, cudaEventDisableTiming);
    cudaEventCreateWithFlags(&evW2, cudaEventDisableTiming);

    cudaEventRecord(evFork, 0);

    // main: w1conv (idx 0)
    w1conv_kernel<<<1024, 256>>>(w1, w1h);

    // s2: router -> scatter, concurrent with w1conv
    cudaStreamWaitEvent(s2, evFork, 0);
    router_kernel<<<T_TOK / 8, 256, 0, s2>>>(x, rw, rb);
    scatter_kernel<<<(T_TOK * 2) / 8, 256, 0, s2>>>(x);
    cudaEventRecord(evScat, s2);

    // s1: w2conv, concurrent with w1conv / router / GEMM1
    cudaStreamWaitEvent(s1, evFork, 0);
    w2conv_kernel<<<1024, 256, 0, s1>>>(w2, w2h);
    cudaEventRecord(evW2, s1);

    // main: persistent GEMM1 (idx 3 -> ncu capture)
    cudaStreamWaitEvent(0, evScat, 0);
    gemm_kernel<DMODEL, DHID, true, 0><<<nsm, 256, DSMEM_BYTES>>>(w1h, b1);

    // main: persistent GEMM2 after w2conv join
    cudaStreamWaitEvent(0, evW2, 0);
    gemm_kernel<DHID, DOUTD, false, 1><<<nsm, 256, DSMEM_BYTES>>>(w2h, b2);

    // combine(+lb tail)
    combine_kernel<<<T_TOK + 1, 256>>>(out, out_size);

    cudaEventDestroy(evFork);
    cudaEventDestroy(evScat);
    cudaEventDestroy(evW2);
    cudaStreamDestroy(s1);
    cudaStreamDestroy(s2);
}

// round 16
// speedup vs baseline: 1.2333x; 1.2333x over previous
#include <cuda_runtime.h>
#include <cuda_fp16.h>
#include <cstdint>
#include <math.h>

// ============================================================================
// MoE (top-2 of 8 experts), D=1024, H=4096, O=1024, T=8192 tokens.
// GEMMs: mma.sync fp16 m16n8k16 fp32-acc, R13 structure (CTA tile 128x256,
// BK=64, 8 warps 2Mx4N warp 64x64, 4-stage cp.async, expert-halved
// GEMM1->GEMM2 stream pipeline) with LDSM (ldmatrix.x4) fragment loads
// replacing scalar LDS (32 -> 8 shared-mem instructions per warp-slab).
// ============================================================================

#define T_TOK   8192
#define DMODEL  1024
#define DHID    4096
#define DOUTD   1024
#define NEXP    8
#define ROWS_CAP 17408
#define MAX_MTILES 136

#define BM 128
#define BN 256
#define BK 64                               // halfs per chunk = 128 B per row

#define SMEM_A_BYTES (BM * BK * 2)          // 16384
#define SMEM_B_BYTES (BN * BK * 2)          // 32768
#define SMEM_STAGE   (SMEM_A_BYTES + SMEM_B_BYTES)  // 49152
#define NSTAGE 4
#define DSMEM_BYTES  (NSTAGE * SMEM_STAGE)  // 196608

// ---------------- device scratch ----------------
__device__ __half g_perm[(size_t)ROWS_CAP * DMODEL];
__device__ __half g_h   [(size_t)ROWS_CAP * DHID];
__device__ float  g_y   [(size_t)ROWS_CAP * DOUTD];
__device__ __half g_w1h [(size_t)NEXP * DHID * DMODEL];
__device__ __half g_w2h [(size_t)NEXP * DOUTD * DHID];
__device__ float g_probs[T_TOK * NEXP];
__device__ float g_gate [T_TOK * 2];
__device__ int   g_topk [T_TOK * 2];
__device__ int   g_spos [T_TOK * 2];
__device__ int   g_counts[NEXP];   // zero-init; reset by setup for next replay
__device__ int   g_cursor[NEXP];
__device__ int   g_offsets[NEXP + 1];
__device__ float g_lb[1];
__device__ int   g_done;

// ---------------- PTX helpers ----------------
__device__ __forceinline__ uint32_t smem_to_u32(const void* p) {
    uint32_t a;
    asm("{ .reg .u64 t; cvta.to.shared.u64 t, %1; cvt.u32.u64 %0, t; }" : "=r"(a) : "l"(p));
    return a;
}
__device__ __forceinline__ uint32_t f2h2(float lo, float hi) {
    uint32_t r;
    asm("cvt.rn.f16x2.f32 %0, %1, %2;" : "=r"(r) : "f"(hi), "f"(lo));
    return r;
}
#define CP_ASYNC16(dst, src) \
    asm volatile("cp.async.cg.shared.global [%0], [%1], 16;" :: "r"(dst), "l"(src) : "memory")
#define CP_COMMIT() asm volatile("cp.async.commit_group;" ::: "memory")
#define CP_WAIT2()  asm volatile("cp.async.wait_group 2;" ::: "memory")
#define CP_WAIT1()  asm volatile("cp.async.wait_group 1;" ::: "memory")
#define CP_WAIT0()  asm volatile("cp.async.wait_group 0;" ::: "memory")

#define LDSM_X4(r0, r1, r2, r3, addr) \
    asm volatile("ldmatrix.sync.aligned.m8n8.x4.shared.b16 {%0,%1,%2,%3}, [%4];" \
                 : "=r"(r0), "=r"(r1), "=r"(r2), "=r"(r3) : "r"(addr))

__device__ __forceinline__ void mma16816(float* c, const uint32_t* a, uint32_t b0, uint32_t b1) {
    asm volatile(
        "mma.sync.aligned.m16n8k16.row.col.f32.f16.f16.f32 "
        "{%0,%1,%2,%3}, {%4,%5,%6,%7}, {%8,%9}, {%0,%1,%2,%3};"
        : "+f"(c[0]), "+f"(c[1]), "+f"(c[2]), "+f"(c[3])
        : "r"(a[0]), "r"(a[1]), "r"(a[2]), "r"(a[3]), "r"(b0), "r"(b1));
}

// ============================================================================
// fp32 -> fp16 weight conversion kernels
// ============================================================================
__global__ void w1conv_kernel(const float* __restrict__ w1, __half* __restrict__ w1h) {
    const int n4 = NEXP * DHID * DMODEL / 4;
    int stride = gridDim.x * blockDim.x;
    for (int i = blockIdx.x * blockDim.x + threadIdx.x; i < n4; i += stride) {
        float4 v = ((const float4*)w1)[i];
        ((uint2*)w1h)[i] = make_uint2(f2h2(v.x, v.y), f2h2(v.z, v.w));
    }
}
__global__ void w2conv_kernel(const float* __restrict__ w2, __half* __restrict__ w2h) {
    const int n4 = NEXP * DOUTD * DHID / 4;
    int stride = gridDim.x * blockDim.x;
    for (int i = blockIdx.x * blockDim.x + threadIdx.x; i < n4; i += stride) {
        float4 u = ((const float4*)w2)[i];
        ((uint2*)w2h)[i] = make_uint2(f2h2(u.x, u.y), f2h2(u.z, u.w));
    }
}

// ============================================================================
// router + (last block) setup
// ============================================================================
__global__ void router_kernel(const float* __restrict__ x, const float* __restrict__ rw,
                              const float* __restrict__ rb) {
    int warp = threadIdx.x >> 5, lane = threadIdx.x & 31;
    int t = blockIdx.x * 8 + warp;
    const float* xp = x + (size_t)t * DMODEL;
    float xr[32];
#pragma unroll
    for (int i = 0; i < 32; i++) xr[i] = xp[i * 32 + lane];
    float lg[NEXP];
#pragma unroll
    for (int e = 0; e < NEXP; e++) {
        const float* wp = rw + e * DMODEL;
        float s = 0.f;
#pragma unroll
        for (int i = 0; i < 32; i++) s += xr[i] * wp[i * 32 + lane];
#pragma unroll
        for (int o = 16; o; o >>= 1) s += __shfl_xor_sync(0xFFFFFFFFu, s, o);
        lg[e] = s + rb[e];
    }
    if (lane == 0) {
        float mx = lg[0];
#pragma unroll
        for (int e = 1; e < NEXP; e++) mx = fmaxf(mx, lg[e]);
        float p[NEXP], sum = 0.f;
#pragma unroll
        for (int e = 0; e < NEXP; e++) { p[e] = expf(lg[e] - mx); sum += p[e]; }
        float inv = 1.f / sum;
#pragma unroll
        for (int e = 0; e < NEXP; e++) { p[e] *= inv; g_probs[t * NEXP + e] = p[e]; }
        int i0 = 0;
#pragma unroll
        for (int e = 1; e < NEXP; e++) if (p[e] > p[i0]) i0 = e;
        int i1 = (i0 == 0) ? 1 : 0;
#pragma unroll
        for (int e = 0; e < NEXP; e++) if (e != i0 && e != i1 && p[e] > p[i1]) i1 = e;
        float w0 = p[i0], w1 = p[i1], ws = 1.f / (w0 + w1);
        g_gate[t * 2 + 0] = w0 * ws;
        g_gate[t * 2 + 1] = w1 * ws;
        g_topk[t * 2 + 0] = i0;
        g_topk[t * 2 + 1] = i1;
        atomicAdd(&g_counts[i0], 1);
        atomicAdd(&g_counts[i1], 1);
        __threadfence();
    }
    __syncthreads();
    __shared__ int s_last;
    if (threadIdx.x == 0) {
        int old = atomicAdd(&g_done, 1);
        s_last = (old == gridDim.x - 1);
    }
    __syncthreads();
    if (!s_last) return;

    __shared__ float sp[NEXP];
    if (warp < NEXP) {
        float s = 0.f;
        for (int tt = lane; tt < T_TOK; tt += 32) s += __ldcg(&g_probs[tt * NEXP + warp]);
#pragma unroll
        for (int o = 16; o; o >>= 1) s += __shfl_xor_sync(0xFFFFFFFFu, s, o);
        if (lane == 0) sp[warp] = s;
    }
    __syncthreads();
    if (threadIdx.x == 0) {
        int off = 0;
        float l = 0.f;
        for (int e = 0; e < NEXP; e++) {
            int c = __ldcg(&g_counts[e]);
            g_offsets[e] = off;
            off += ((c + BM - 1) / BM) * BM;
            g_cursor[e] = 0;
            g_counts[e] = 0;   // reset for next graph replay
            l += ((float)c / (float)(T_TOK * 2)) * (sp[e] / (float)T_TOK);
        }
        g_offsets[NEXP] = off;
        g_lb[0] = 0.01f * (float)NEXP * l;
        g_done = 0;
    }
}

// ============================================================================
// gather: converts x rows to fp16 in grouped layout
// ============================================================================
__global__ void scatter_kernel(const float* __restrict__ x) {
    int wslot = blockIdx.x * 8 + (threadIdx.x >> 5);
    int lane = threadIdx.x & 31;
    int t = wslot >> 1, k = wslot & 1;
    int e = g_topk[t * 2 + k];
    int pos = 0;
    if (lane == 0) {
        pos = g_offsets[e] + atomicAdd(&g_cursor[e], 1);
        g_spos[t * 2 + k] = pos;
    }
    pos = __shfl_sync(0xFFFFFFFFu, pos, 0);
    const float4* src = (const float4*)(x + (size_t)t * DMODEL);
    uint2* dst = (uint2*)(g_perm + (size_t)pos * DMODEL);
#pragma unroll
    for (int j = 0; j < 8; j++) {
        float4 v = src[lane + j * 32];
        dst[lane + j * 32] = make_uint2(f2h2(v.x, v.y), f2h2(v.z, v.w));
    }
}

// ============================================================================
// Grouped fp16 GEMM (expert range [elo,ehi)), LDSM fragment loads.
// MODE 0: A=g_perm -> C=g_h (relu, fp16). MODE 1: A=g_h -> C=g_y (f32).
// ============================================================================
template <int KTOT, int NTOT, bool RELU, int MODE>
__global__ __launch_bounds__(256, 1) void gemm_kernel(const __half* __restrict__ Bw,
                                                      const float* __restrict__ bias,
                                                      int elo, int ehi) {
    const __half* A = (MODE == 0) ? g_perm : g_h;

    int row0 = (int)blockIdx.y * BM;
    if (row0 < g_offsets[elo] || row0 >= g_offsets[ehi]) return;
    int e = elo;
#pragma unroll
    for (int i = 1; i < NEXP; i++) if (i > elo && i < ehi && row0 >= g_offsets[i]) e = i;
    int n0 = blockIdx.x * BN;

    extern __shared__ char smem[];
    uint32_t sb = smem_to_u32(smem);
    int tid = threadIdx.x;
    int wid = tid >> 5, lane = tid & 31;
    int g = lane >> 2, t = lane & 3;
    int wm = wid >> 2;
    int wn = wid & 3;

    // ---- per-lane LDSM address invariants ----
    // A tile mt: lanes 0-15 -> rows 0-15 (k-chunk c0), lanes 16-31 -> rows 0-15
    // (k-chunk c0+1). Gives r0..r3 = a0..a3 of mma.m16n8k16.
    int a_row[4], a_rx[4];
#pragma unroll
    for (int mt = 0; mt < 4; mt++) {
        int r = wm * 64 + mt * 16 + (lane & 15);
        a_row[mt] = r * 128;
        a_rx[mt] = r & 7;
    }
    int a_cs = lane >> 4;                  // chunk select 0/1
    // B nt-pair ntp (nt = 2*ntp): lanes 0-7 -> nt rows, chunk c0; 8-15 -> nt
    // rows chunk c0+1; 16-23 -> nt+1 rows chunk c0; 24-31 -> nt+1 chunk c0+1.
    // Gives r0..r3 = b0(nt), b1(nt), b0(nt+1), b1(nt+1).
    int b_row[4], b_rx[4];
#pragma unroll
    for (int ntp = 0; ntp < 4; ntp++) {
        int r = wn * 64 + (2 * ntp + (lane >> 4)) * 8 + (lane & 7);
        b_row[ntp] = r * 128;
        b_rx[ntp] = r & 7;
    }
    int b_cs = (lane >> 3) & 1;            // chunk select 0/1

    const __half* Ag = A + (size_t)row0 * KTOT;
    const __half* Bg = Bw + (size_t)e * NTOT * KTOT + (size_t)n0 * KTOT;

    auto load_chunk = [&](int it, int buf) {
        int k0 = it * BK;
        uint32_t sA = sb + buf * SMEM_STAGE;
        uint32_t sB = sA + SMEM_A_BYTES;
#pragma unroll
        for (int i = 0; i < 4; i++) {           // A: 128 rows x 8 x 16B
            int idx = tid + i * 256;
            int r = idx >> 3, c8 = idx & 7;
            uint32_t dst = sA + (uint32_t)(r * 8 + (c8 ^ (r & 7))) * 16;
            CP_ASYNC16(dst, Ag + (size_t)r * KTOT + k0 + c8 * 8);
        }
#pragma unroll
        for (int i = 0; i < 8; i++) {           // B: 256 rows x 8 x 16B
            int idx = tid + i * 256;
            int r = idx >> 3, c8 = idx & 7;
            uint32_t dst = sB + (uint32_t)(r * 8 + (c8 ^ (r & 7))) * 16;
            CP_ASYNC16(dst, Bg + (size_t)r * KTOT + k0 + c8 * 8);
        }
        CP_COMMIT();
    };

    float acc[4][8][4];
#pragma unroll
    for (int mt = 0; mt < 4; mt++)
#pragma unroll
        for (int nt = 0; nt < 8; nt++)
#pragma unroll
            for (int j = 0; j < 4; j++) acc[mt][nt][j] = 0.f;

    constexpr int NIT = KTOT / BK;     // 16 (GEMM1) / 64 (GEMM2)
    load_chunk(0, 0);
    load_chunk(1, 1);
    load_chunk(2, 2);

    for (int it = 0; it < NIT; ++it) {
        int buf = it & 3;
        if (it < NIT - 2)      { CP_WAIT2(); }
        else if (it == NIT - 2){ CP_WAIT1(); }
        else                   { CP_WAIT0(); }
        __syncthreads();
        if (it + 3 < NIT) load_chunk(it + 3, (it + 3) & 3);

        uint32_t sA = sb + buf * SMEM_STAGE;
        uint32_t sB = sA + SMEM_A_BYTES;

        // fragment loader for k-slab kk: A 4x LDSM.x4, B 4x LDSM.x4
        auto lfrag = [&](int kk, uint32_t* a_f, uint32_t* b_f) {
            int c0 = 2 * kk;
#pragma unroll
            for (int mt = 0; mt < 4; mt++) {
                uint32_t addr = sA + (uint32_t)a_row[mt]
                              + (uint32_t)(((c0 + a_cs) ^ a_rx[mt]) << 4);
                LDSM_X4(a_f[mt * 4 + 0], a_f[mt * 4 + 1],
                        a_f[mt * 4 + 2], a_f[mt * 4 + 3], addr);
            }
#pragma unroll
            for (int ntp = 0; ntp < 4; ntp++) {
                uint32_t addr = sB + (uint32_t)b_row[ntp]
                              + (uint32_t)(((c0 + b_cs) ^ b_rx[ntp]) << 4);
                LDSM_X4(b_f[ntp * 4 + 0], b_f[ntp * 4 + 1],
                        b_f[ntp * 4 + 2], b_f[ntp * 4 + 3], addr);
            }
        };

        uint32_t afr[2][16], bfr[2][16];
        lfrag(0, afr[0], bfr[0]);
#pragma unroll
        for (int kk = 0; kk < 4; kk++) {
            int cur = kk & 1;
            if (kk < 3) lfrag(kk + 1, afr[cur ^ 1], bfr[cur ^ 1]);
#pragma unroll
            for (int nt = 0; nt < 8; nt++)
#pragma unroll
                for (int mt = 0; mt < 4; mt++)
                    mma16816(acc[mt][nt], &afr[cur][mt * 4],
                             bfr[cur][nt * 2], bfr[cur][nt * 2 + 1]);
        }
    }

    // ---- epilogue ----
    const float* bp = bias + (size_t)e * NTOT + n0 + wn * 64;
#pragma unroll
    for (int nt = 0; nt < 8; nt++) {
        int col = nt * 8 + 2 * t;
        float2 bv = *(const float2*)(bp + col);
#pragma unroll
        for (int mt = 0; mt < 4; mt++) {
            int r0 = row0 + wm * 64 + mt * 16 + g;
            float v[4];
            v[0] = acc[mt][nt][0] + bv.x; v[1] = acc[mt][nt][1] + bv.y;
            v[2] = acc[mt][nt][2] + bv.x; v[3] = acc[mt][nt][3] + bv.y;
            if (RELU) {
#pragma unroll
                for (int j = 0; j < 4; j++) v[j] = fmaxf(v[j], 0.f);
            }
            if (MODE == 0) {
                uint32_t* cp0 = (uint32_t*)(g_h + (size_t)r0 * NTOT + n0 + wn * 64 + col);
                cp0[0] = f2h2(v[0], v[1]);
                *(uint32_t*)((__half*)cp0 + (size_t)8 * NTOT) = f2h2(v[2], v[3]);
            } else {
                float* cp0 = g_y + (size_t)r0 * NTOT + n0 + wn * 64 + col;
                *(float2*)cp0 = make_float2(v[0], v[1]);
                *(float2*)(cp0 + (size_t)8 * NTOT) = make_float2(v[2], v[3]);
            }
        }
    }
}

// ============================================================================
// combine (+ lb tail written by the extra trailing block)
// ============================================================================
__global__ void combine_kernel(float* __restrict__ out, int out_size) {
    int t = blockIdx.x;
    if (t >= T_TOK) {
        long long tail = (long long)out_size - (long long)T_TOK * DOUTD;
        if (threadIdx.x < tail && threadIdx.x < 256)
            out[(size_t)T_TOK * DOUTD + threadIdx.x] = g_lb[0];
        return;
    }
    int d4 = threadIdx.x;
    float w0 = g_gate[t * 2 + 0], w1 = g_gate[t * 2 + 1];
    int p0 = g_spos[t * 2 + 0], p1 = g_spos[t * 2 + 1];
    float4 y0 = ((const float4*)(g_y + (size_t)p0 * DOUTD))[d4];
    float4 y1 = ((const float4*)(g_y + (size_t)p1 * DOUTD))[d4];
    float4 o;
    o.x = w0 * y0.x + w1 * y1.x;
    o.y = w0 * y0.y + w1 * y1.y;
    o.z = w0 * y0.z + w1 * y1.z;
    o.w = w0 * y0.w + w1 * y1.w;
    ((float4*)(out + (size_t)t * DOUTD))[d4] = o;
}

// ============================================================================
extern "C" void kernel_launch(void* const* d_in, const int* in_sizes, int n_in,
                              void* d_out, int out_size) {
    const float* x  = (const float*)d_in[0];
    const float* rw = (const float*)d_in[1];
    const float* rb = (const float*)d_in[2];
    const float* w1 = (const float*)d_in[3];
    const float* b1 = (const float*)d_in[4];
    const float* w2 = (const float*)d_in[5];
    const float* b2 = (const float*)d_in[6];
    float* out = (float*)d_out;

    cudaFuncSetAttribute(gemm_kernel<DMODEL, DHID, true, 0>,
                         cudaFuncAttributeMaxDynamicSharedMemorySize, DSMEM_BYTES);
    cudaFuncSetAttribute(gemm_kernel<DHID, DOUTD, false, 1>,
                         cudaFuncAttributeMaxDynamicSharedMemorySize, DSMEM_BYTES);

    __half* w1h; cudaGetSymbolAddress((void**)&w1h, g_w1h);
    __half* w2h; cudaGetSymbolAddress((void**)&w2h, g_w2h);

    cudaStream_t s1, s2;
    cudaStreamCreateWithFlags(&s1, cudaStreamNonBlocking);
    cudaStreamCreateWithFlags(&s2, cudaStreamNonBlocking);
    cudaEvent_t evFork, evScat, evG1A, evG1B, evG2;
    cudaEventCreateWithFlags(&evFork, cudaEventDisableTiming);
    cudaEventCreateWithFlags(&evScat, cudaEventDisableTiming);
    cudaEventCreateWithFlags(&evG1A, cudaEventDisableTiming);
    cudaEventCreateWithFlags(&evG1B, cudaEventDisableTiming);
    cudaEventCreateWithFlags(&evG2, cudaEventDisableTiming);

    cudaEventRecord(evFork, 0);

    // main: w1conv (idx 0)
    w1conv_kernel<<<1024, 256>>>(w1, w1h);

    // s2: router -> scatter, concurrent with w1conv
    cudaStreamWaitEvent(s2, evFork, 0);
    router_kernel<<<T_TOK / 8, 256, 0, s2>>>(x, rw, rb);
    scatter_kernel<<<(T_TOK * 2) / 8, 256, 0, s2>>>(x);
    cudaEventRecord(evScat, s2);

    // main: GEMM1 expert halves (idx 3 = half A, the ncu-captured launch)
    cudaStreamWaitEvent(0, evScat, 0);
    gemm_kernel<DMODEL, DHID, true, 0>
        <<<dim3(DHID / BN, MAX_MTILES, 1), 256, DSMEM_BYTES>>>(w1h, b1, 0, 4);
    cudaEventRecord(evG1A, 0);
    gemm_kernel<DMODEL, DHID, true, 0>
        <<<dim3(DHID / BN, MAX_MTILES, 1), 256, DSMEM_BYTES>>>(w1h, b1, 4, 8);
    cudaEventRecord(evG1B, 0);

    // s1: w2conv (overlaps GEMM1), then GEMM2 halves pipelined behind GEMM1
    cudaStreamWaitEvent(s1, evFork, 0);
    w2conv_kernel<<<1024, 256, 0, s1>>>(w2, w2h);
    cudaStreamWaitEvent(s1, evG1A, 0);
    gemm_kernel<DHID, DOUTD, false, 1>
        <<<dim3(DOUTD / BN, MAX_MTILES, 1), 256, DSMEM_BYTES, s1>>>(w2h, b2, 0, 4);
    cudaStreamWaitEvent(s1, evG1B, 0);
    gemm_kernel<DHID, DOUTD, false, 1>
        <<<dim3(DOUTD / BN, MAX_MTILES, 1), 256, DSMEM_BYTES, s1>>>(w2h, b2, 4, 8);
    cudaEventRecord(evG2, s1);

    // join, then combine(+lb tail)
    cudaStreamWaitEvent(0, evG2, 0);
    combine_kernel<<<T_TOK + 1, 256>>>(out, out_size);

    cudaEventDestroy(evFork);
    cudaEventDestroy(evScat);
    cudaEventDestroy(evG1A);
    cudaEventDestroy(evG1B);
    cudaEventDestroy(evG2);
    cudaStreamDestroy(s1);
    cudaStreamDestroy(s2);
}

// round 17
// speedup vs baseline: 1.3133x; 1.0649x over previous
#include <cuda_runtime.h>
#include <cuda_fp16.h>
#include <cstdint>
#include <math.h>

// ============================================================================
// MoE (top-2 of 8 experts), D=1024, H=4096, O=1024, T=8192 tokens.
// GEMMs: mma.sync fp16 m16n8k16 fp32-acc. CTA tile 128x128, warp tile 64x32,
// 8 warps, LDSM fragment loads, 3-stage cp.async, __launch_bounds__(256,2)
// -> 2 CTAs/SM (two independent barrier domains per SM fill each other's
// chunk-boundary pipe drains). Expert-halved GEMM1->GEMM2 stream pipeline;
// router/scatter overlap w1conv; w2conv overlaps GEMM1.
// ============================================================================

#define T_TOK   8192
#define DMODEL  1024
#define DHID    4096
#define DOUTD   1024
#define NEXP    8
#define ROWS_CAP 17408
#define MAX_MTILES 136

#define BM 128
#define BN 128
#define BK 64                               // halfs per chunk = 128 B per row

#define SMEM_A_BYTES (BM * BK * 2)          // 16384
#define SMEM_B_BYTES (BN * BK * 2)          // 16384
#define SMEM_STAGE   (SMEM_A_BYTES + SMEM_B_BYTES)  // 32768
#define NSTAGE 3
#define DSMEM_BYTES  (NSTAGE * SMEM_STAGE)  // 98304 (x2 CTAs = 192K/SM)

// ---------------- device scratch ----------------
__device__ __half g_perm[(size_t)ROWS_CAP * DMODEL];
__device__ __half g_h   [(size_t)ROWS_CAP * DHID];
__device__ float  g_y   [(size_t)ROWS_CAP * DOUTD];
__device__ __half g_w1h [(size_t)NEXP * DHID * DMODEL];
__device__ __half g_w2h [(size_t)NEXP * DOUTD * DHID];
__device__ float g_probs[T_TOK * NEXP];
__device__ float g_gate [T_TOK * 2];
__device__ int   g_topk [T_TOK * 2];
__device__ int   g_spos [T_TOK * 2];
__device__ int   g_counts[NEXP];   // zero-init; reset by setup for next replay
__device__ int   g_cursor[NEXP];
__device__ int   g_offsets[NEXP + 1];
__device__ float g_lb[1];
__device__ int   g_done;

// ---------------- PTX helpers ----------------
__device__ __forceinline__ uint32_t smem_to_u32(const void* p) {
    uint32_t a;
    asm("{ .reg .u64 t; cvta.to.shared.u64 t, %1; cvt.u32.u64 %0, t; }" : "=r"(a) : "l"(p));
    return a;
}
__device__ __forceinline__ uint32_t f2h2(float lo, float hi) {
    uint32_t r;
    asm("cvt.rn.f16x2.f32 %0, %1, %2;" : "=r"(r) : "f"(hi), "f"(lo));
    return r;
}
#define CP_ASYNC16(dst, src) \
    asm volatile("cp.async.cg.shared.global [%0], [%1], 16;" :: "r"(dst), "l"(src) : "memory")
#define CP_COMMIT() asm volatile("cp.async.commit_group;" ::: "memory")
#define CP_WAIT1()  asm volatile("cp.async.wait_group 1;" ::: "memory")
#define CP_WAIT0()  asm volatile("cp.async.wait_group 0;" ::: "memory")

#define LDSM_X4(r0, r1, r2, r3, addr) \
    asm volatile("ldmatrix.sync.aligned.m8n8.x4.shared.b16 {%0,%1,%2,%3}, [%4];" \
                 : "=r"(r0), "=r"(r1), "=r"(r2), "=r"(r3) : "r"(addr))

__device__ __forceinline__ void mma16816(float* c, const uint32_t* a, uint32_t b0, uint32_t b1) {
    asm volatile(
        "mma.sync.aligned.m16n8k16.row.col.f32.f16.f16.f32 "
        "{%0,%1,%2,%3}, {%4,%5,%6,%7}, {%8,%9}, {%0,%1,%2,%3};"
        : "+f"(c[0]), "+f"(c[1]), "+f"(c[2]), "+f"(c[3])
        : "r"(a[0]), "r"(a[1]), "r"(a[2]), "r"(a[3]), "r"(b0), "r"(b1));
}

// ============================================================================
// fp32 -> fp16 weight conversion kernels
// ============================================================================
__global__ void w1conv_kernel(const float* __restrict__ w1, __half* __restrict__ w1h) {
    const int n4 = NEXP * DHID * DMODEL / 4;
    int stride = gridDim.x * blockDim.x;
    for (int i = blockIdx.x * blockDim.x + threadIdx.x; i < n4; i += stride) {
        float4 v = ((const float4*)w1)[i];
        ((uint2*)w1h)[i] = make_uint2(f2h2(v.x, v.y), f2h2(v.z, v.w));
    }
}
__global__ void w2conv_kernel(const float* __restrict__ w2, __half* __restrict__ w2h) {
    const int n4 = NEXP * DOUTD * DHID / 4;
    int stride = gridDim.x * blockDim.x;
    for (int i = blockIdx.x * blockDim.x + threadIdx.x; i < n4; i += stride) {
        float4 u = ((const float4*)w2)[i];
        ((uint2*)w2h)[i] = make_uint2(f2h2(u.x, u.y), f2h2(u.z, u.w));
    }
}

// ============================================================================
// router + (last block) setup
// ============================================================================
__global__ void router_kernel(const float* __restrict__ x, const float* __restrict__ rw,
                              const float* __restrict__ rb) {
    int warp = threadIdx.x >> 5, lane = threadIdx.x & 31;
    int t = blockIdx.x * 8 + warp;
    const float* xp = x + (size_t)t * DMODEL;
    float xr[32];
#pragma unroll
    for (int i = 0; i < 32; i++) xr[i] = xp[i * 32 + lane];
    float lg[NEXP];
#pragma unroll
    for (int e = 0; e < NEXP; e++) {
        const float* wp = rw + e * DMODEL;
        float s = 0.f;
#pragma unroll
        for (int i = 0; i < 32; i++) s += xr[i] * wp[i * 32 + lane];
#pragma unroll
        for (int o = 16; o; o >>= 1) s += __shfl_xor_sync(0xFFFFFFFFu, s, o);
        lg[e] = s + rb[e];
    }
    if (lane == 0) {
        float mx = lg[0];
#pragma unroll
        for (int e = 1; e < NEXP; e++) mx = fmaxf(mx, lg[e]);
        float p[NEXP], sum = 0.f;
#pragma unroll
        for (int e = 0; e < NEXP; e++) { p[e] = expf(lg[e] - mx); sum += p[e]; }
        float inv = 1.f / sum;
#pragma unroll
        for (int e = 0; e < NEXP; e++) { p[e] *= inv; g_probs[t * NEXP + e] = p[e]; }
        int i0 = 0;
#pragma unroll
        for (int e = 1; e < NEXP; e++) if (p[e] > p[i0]) i0 = e;
        int i1 = (i0 == 0) ? 1 : 0;
#pragma unroll
        for (int e = 0; e < NEXP; e++) if (e != i0 && e != i1 && p[e] > p[i1]) i1 = e;
        float w0 = p[i0], w1 = p[i1], ws = 1.f / (w0 + w1);
        g_gate[t * 2 + 0] = w0 * ws;
        g_gate[t * 2 + 1] = w1 * ws;
        g_topk[t * 2 + 0] = i0;
        g_topk[t * 2 + 1] = i1;
        atomicAdd(&g_counts[i0], 1);
        atomicAdd(&g_counts[i1], 1);
        __threadfence();
    }
    __syncthreads();
    __shared__ int s_last;
    if (threadIdx.x == 0) {
        int old = atomicAdd(&g_done, 1);
        s_last = (old == gridDim.x - 1);
    }
    __syncthreads();
    if (!s_last) return;

    __shared__ float sp[NEXP];
    if (warp < NEXP) {
        float s = 0.f;
        for (int tt = lane; tt < T_TOK; tt += 32) s += __ldcg(&g_probs[tt * NEXP + warp]);
#pragma unroll
        for (int o = 16; o; o >>= 1) s += __shfl_xor_sync(0xFFFFFFFFu, s, o);
        if (lane == 0) sp[warp] = s;
    }
    __syncthreads();
    if (threadIdx.x == 0) {
        int off = 0;
        float l = 0.f;
        for (int e = 0; e < NEXP; e++) {
            int c = __ldcg(&g_counts[e]);
            g_offsets[e] = off;
            off += ((c + BM - 1) / BM) * BM;
            g_cursor[e] = 0;
            g_counts[e] = 0;   // reset for next graph replay
            l += ((float)c / (float)(T_TOK * 2)) * (sp[e] / (float)T_TOK);
        }
        g_offsets[NEXP] = off;
        g_lb[0] = 0.01f * (float)NEXP * l;
        g_done = 0;
    }
}

// ============================================================================
// gather: converts x rows to fp16 in grouped layout
// ============================================================================
__global__ void scatter_kernel(const float* __restrict__ x) {
    int wslot = blockIdx.x * 8 + (threadIdx.x >> 5);
    int lane = threadIdx.x & 31;
    int t = wslot >> 1, k = wslot & 1;
    int e = g_topk[t * 2 + k];
    int pos = 0;
    if (lane == 0) {
        pos = g_offsets[e] + atomicAdd(&g_cursor[e], 1);
        g_spos[t * 2 + k] = pos;
    }
    pos = __shfl_sync(0xFFFFFFFFu, pos, 0);
    const float4* src = (const float4*)(x + (size_t)t * DMODEL);
    uint2* dst = (uint2*)(g_perm + (size_t)pos * DMODEL);
#pragma unroll
    for (int j = 0; j < 8; j++) {
        float4 v = src[lane + j * 32];
        dst[lane + j * 32] = make_uint2(f2h2(v.x, v.y), f2h2(v.z, v.w));
    }
}

// ============================================================================
// Grouped fp16 GEMM (expert range [elo,ehi)). CTA 128x128, warp 64x32,
// LDSM fragments (single-buffered), 3-stage cp.async, 2 CTAs/SM.
// MODE 0: A=g_perm -> C=g_h (relu, fp16). MODE 1: A=g_h -> C=g_y (f32).
// ============================================================================
template <int KTOT, int NTOT, bool RELU, int MODE>
__global__ __launch_bounds__(256, 2) void gemm_kernel(const __half* __restrict__ Bw,
                                                      const float* __restrict__ bias,
                                                      int elo, int ehi) {
    const __half* A = (MODE == 0) ? g_perm : g_h;

    int row0 = (int)blockIdx.y * BM;
    if (row0 < g_offsets[elo] || row0 >= g_offsets[ehi]) return;
    int e = elo;
#pragma unroll
    for (int i = 1; i < NEXP; i++) if (i > elo && i < ehi && row0 >= g_offsets[i]) e = i;
    int n0 = blockIdx.x * BN;

    extern __shared__ char smem[];
    uint32_t sb = smem_to_u32(smem);
    int tid = threadIdx.x;
    int wid = tid >> 5, lane = tid & 31;
    int g = lane >> 2, t = lane & 3;
    int wm = wid >> 2;          // 0..1 -> m offset wm*64
    int wn = wid & 3;           // 0..3 -> n offset wn*32

    // ---- per-lane LDSM address invariants (same mapping as R16) ----
    int a_row[4], a_rx[4];
#pragma unroll
    for (int mt = 0; mt < 4; mt++) {
        int r = wm * 64 + mt * 16 + (lane & 15);
        a_row[mt] = r * 128;
        a_rx[mt] = r & 7;
    }
    int a_cs = lane >> 4;                  // chunk select 0/1
    int b_row[2], b_rx[2];
#pragma unroll
    for (int ntp = 0; ntp < 2; ntp++) {
        int r = wn * 32 + (2 * ntp + (lane >> 4)) * 8 + (lane & 7);
        b_row[ntp] = r * 128;
        b_rx[ntp] = r & 7;
    }
    int b_cs = (lane >> 3) & 1;            // chunk select 0/1

    const __half* Ag = A + (size_t)row0 * KTOT;
    const __half* Bg = Bw + (size_t)e * NTOT * KTOT + (size_t)n0 * KTOT;

    auto load_chunk = [&](int it, int buf) {
        int k0 = it * BK;
        uint32_t sA = sb + buf * SMEM_STAGE;
        uint32_t sB = sA + SMEM_A_BYTES;
#pragma unroll
        for (int i = 0; i < 4; i++) {           // A: 128 rows x 8 x 16B
            int idx = tid + i * 256;
            int r = idx >> 3, c8 = idx & 7;
            uint32_t dst = sA + (uint32_t)(r * 8 + (c8 ^ (r & 7))) * 16;
            CP_ASYNC16(dst, Ag + (size_t)r * KTOT + k0 + c8 * 8);
        }
#pragma unroll
        for (int i = 0; i < 4; i++) {           // B: 128 rows x 8 x 16B
            int idx = tid + i * 256;
            int r = idx >> 3, c8 = idx & 7;
            uint32_t dst = sB + (uint32_t)(r * 8 + (c8 ^ (r & 7))) * 16;
            CP_ASYNC16(dst, Bg + (size_t)r * KTOT + k0 + c8 * 8);
        }
        CP_COMMIT();
    };

    float acc[4][4][4];
#pragma unroll
    for (int mt = 0; mt < 4; mt++)
#pragma unroll
        for (int nt = 0; nt < 4; nt++)
#pragma unroll
            for (int j = 0; j < 4; j++) acc[mt][nt][j] = 0.f;

    constexpr int NIT = KTOT / BK;     // 16 (GEMM1) / 64 (GEMM2)
    load_chunk(0, 0);
    load_chunk(1, 1);

    int buf = 0;
    for (int it = 0; it < NIT; ++it) {
        if (it == NIT - 1) { CP_WAIT0(); } else { CP_WAIT1(); }
        __syncthreads();
        if (it + 2 < NIT) {
            int nb = buf + 2; if (nb >= NSTAGE) nb -= NSTAGE;
            load_chunk(it + 2, nb);
        }

        uint32_t sA = sb + buf * SMEM_STAGE;
        uint32_t sB = sA + SMEM_A_BYTES;

#pragma unroll
        for (int kk = 0; kk < 4; kk++) {        // k-slab of 16 halfs
            int c0 = 2 * kk;
            uint32_t afr[16], bfr[8];
#pragma unroll
            for (int mt = 0; mt < 4; mt++) {
                uint32_t addr = sA + (uint32_t)a_row[mt]
                              + (uint32_t)(((c0 + a_cs) ^ a_rx[mt]) << 4);
                LDSM_X4(afr[mt * 4 + 0], afr[mt * 4 + 1],
                        afr[mt * 4 + 2], afr[mt * 4 + 3], addr);
            }
#pragma unroll
            for (int ntp = 0; ntp < 2; ntp++) {
                uint32_t addr = sB + (uint32_t)b_row[ntp]
                              + (uint32_t)(((c0 + b_cs) ^ b_rx[ntp]) << 4);
                LDSM_X4(bfr[ntp * 4 + 0], bfr[ntp * 4 + 1],
                        bfr[ntp * 4 + 2], bfr[ntp * 4 + 3], addr);
            }
#pragma unroll
            for (int nt = 0; nt < 4; nt++)
#pragma unroll
                for (int mt = 0; mt < 4; mt++)
                    mma16816(acc[mt][nt], &afr[mt * 4],
                             bfr[nt * 2], bfr[nt * 2 + 1]);
        }
        buf = (buf == NSTAGE - 1) ? 0 : buf + 1;
    }

    // ---- epilogue ----
    const float* bp = bias + (size_t)e * NTOT + n0 + wn * 32;
#pragma unroll
    for (int nt = 0; nt < 4; nt++) {
        int col = nt * 8 + 2 * t;
        float2 bv = *(const float2*)(bp + col);
#pragma unroll
        for (int mt = 0; mt < 4; mt++) {
            int r0 = row0 + wm * 64 + mt * 16 + g;
            float v[4];
            v[0] = acc[mt][nt][0] + bv.x; v[1] = acc[mt][nt][1] + bv.y;
            v[2] = acc[mt][nt][2] + bv.x; v[3] = acc[mt][nt][3] + bv.y;
            if (RELU) {
#pragma unroll
                for (int j = 0; j < 4; j++) v[j] = fmaxf(v[j], 0.f);
            }
            if (MODE == 0) {
                uint32_t* cp0 = (uint32_t*)(g_h + (size_t)r0 * NTOT + n0 + wn * 32 + col);
                cp0[0] = f2h2(v[0], v[1]);
                *(uint32_t*)((__half*)cp0 + (size_t)8 * NTOT) = f2h2(v[2], v[3]);
            } else {
                float* cp0 = g_y + (size_t)r0 * NTOT + n0 + wn * 32 + col;
                *(float2*)cp0 = make_float2(v[0], v[1]);
                *(float2*)(cp0 + (size_t)8 * NTOT) = make_float2(v[2], v[3]);
            }
        }
    }
}

// ============================================================================
// combine (+ lb tail written by the extra trailing block)
// ============================================================================
__global__ void combine_kernel(float* __restrict__ out, int out_size) {
    int t = blockIdx.x;
    if (t >= T_TOK) {
        long long tail = (long long)out_size - (long long)T_TOK * DOUTD;
        if (threadIdx.x < tail && threadIdx.x < 256)
            out[(size_t)T_TOK * DOUTD + threadIdx.x] = g_lb[0];
        return;
    }
    int d4 = threadIdx.x;
    float w0 = g_gate[t * 2 + 0], w1 = g_gate[t * 2 + 1];
    int p0 = g_spos[t * 2 + 0], p1 = g_spos[t * 2 + 1];
    float4 y0 = ((const float4*)(g_y + (size_t)p0 * DOUTD))[d4];
    float4 y1 = ((const float4*)(g_y + (size_t)p1 * DOUTD))[d4];
    float4 o;
    o.x = w0 * y0.x + w1 * y1.x;
    o.y = w0 * y0.y + w1 * y1.y;
    o.z = w0 * y0.z + w1 * y1.z;
    o.w = w0 * y0.w + w1 * y1.w;
    ((float4*)(out + (size_t)t * DOUTD))[d4] = o;
}

// ============================================================================
extern "C" void kernel_launch(void* const* d_in, const int* in_sizes, int n_in,
                              void* d_out, int out_size) {
    const float* x  = (const float*)d_in[0];
    const float* rw = (const float*)d_in[1];
    const float* rb = (const float*)d_in[2];
    const float* w1 = (const float*)d_in[3];
    const float* b1 = (const float*)d_in[4];
    const float* w2 = (const float*)d_in[5];
    const float* b2 = (const float*)d_in[6];
    float* out = (float*)d_out;

    cudaFuncSetAttribute(gemm_kernel<DMODEL, DHID, true, 0>,
                         cudaFuncAttributeMaxDynamicSharedMemorySize, DSMEM_BYTES);
    cudaFuncSetAttribute(gemm_kernel<DHID, DOUTD, false, 1>,
                         cudaFuncAttributeMaxDynamicSharedMemorySize, DSMEM_BYTES);

    __half* w1h; cudaGetSymbolAddress((void**)&w1h, g_w1h);
    __half* w2h; cudaGetSymbolAddress((void**)&w2h, g_w2h);

    cudaStream_t s1, s2;
    cudaStreamCreateWithFlags(&s1, cudaStreamNonBlocking);
    cudaStreamCreateWithFlags(&s2, cudaStreamNonBlocking);
    cudaEvent_t evFork, evScat, evG1A, evG1B, evG2;
    cudaEventCreateWithFlags(&evFork, cudaEventDisableTiming);
    cudaEventCreateWithFlags(&evScat, cudaEventDisableTiming);
    cudaEventCreateWithFlags(&evG1A, cudaEventDisableTiming);
    cudaEventCreateWithFlags(&evG1B, cudaEventDisableTiming);
    cudaEventCreateWithFlags(&evG2, cudaEventDisableTiming);

    cudaEventRecord(evFork, 0);

    // main: w1conv (idx 0)
    w1conv_kernel<<<1024, 256>>>(w1, w1h);

    // s2: router -> scatter, concurrent with w1conv
    cudaStreamWaitEvent(s2, evFork, 0);
    router_kernel<<<T_TOK / 8, 256, 0, s2>>>(x, rw, rb);
    scatter_kernel<<<(T_TOK * 2) / 8, 256, 0, s2>>>(x);
    cudaEventRecord(evScat, s2);

    // main: GEMM1 expert halves (idx 3 = half A, the ncu-captured launch)
    cudaStreamWaitEvent(0, evScat, 0);
    gemm_kernel<DMODEL, DHID, true, 0>
        <<<dim3(DHID / BN, MAX_MTILES, 1), 256, DSMEM_BYTES>>>(w1h, b1, 0, 4);
    cudaEventRecord(evG1A, 0);
    gemm_kernel<DMODEL, DHID, true, 0>
        <<<dim3(DHID / BN, MAX_MTILES, 1), 256, DSMEM_BYTES>>>(w1h, b1, 4, 8);
    cudaEventRecord(evG1B, 0);

    // s1: w2conv (overlaps GEMM1), then GEMM2 halves pipelined behind GEMM1
    cudaStreamWaitEvent(s1, evFork, 0);
    w2conv_kernel<<<1024, 256, 0, s1>>>(w2, w2h);
    cudaStreamWaitEvent(s1, evG1A, 0);
    gemm_kernel<DHID, DOUTD, false, 1>
        <<<dim3(DOUTD / BN, MAX_MTILES, 1), 256, DSMEM_BYTES, s1>>>(w2h, b2, 0, 4);
    cudaStreamWaitEvent(s1, evG1B, 0);
    gemm_kernel<DHID, DOUTD, false, 1>
        <<<dim3(DOUTD / BN, MAX_MTILES, 1), 256, DSMEM_BYTES, s1>>>(w2h, b2, 4, 8);
    cudaEventRecord(evG2, s1);

    // join, then combine(+lb tail)
    cudaStreamWaitEvent(0, evG2, 0);
    combine_kernel<<<T_TOK + 1, 256>>>(out, out_size);

    cudaEventDestroy(evFork);
    cudaEventDestroy(evScat);
    cudaEventDestroy(evG1A);
    cudaEventDestroy(evG1B);
    cudaEventDestroy(evG2);
    cudaStreamDestroy(s1);
    cudaStreamDestroy(s2);
}